// round 5
// baseline (speedup 1.0000x reference)
#include <cuda_runtime.h>
#include <math.h>

#define B 8
#define NEV 100000
#define NPARAMS 4000000
#define EPSF 1.1920928955078125e-07f

// Accumulator: float2 per pixel (x=num, y=den), 16B-aligned for v4 REDs.
// Zeroed at module load; k_evreduce restores zeros after reading -> no zero pass.
#define ACCUM_F2 2785280
__device__ __align__(16) float2 g_accum[ACCUM_F2];
__device__ float g_tref[B][2][2];       // [b][m][0]=first(bwd), [1]=last(fwd)

// Interleaved flow (fx,fy) per pixel: level offsets {0,8192,40960,172032}
#define FI_TOT 696320
__device__ __align__(16) float2 g_fint[FI_TOT];
__device__ __constant__ int c_fioff[4] = {0, 8192, 40960, 172032};

#define NB_SM 512
#define NB_WD 256
#define NB_ER 1024
__device__ double g_part_sm[NB_SM];
__device__ double g_part_wd[NB_WD];
__device__ double g_part_er[NB_ER];
__device__ unsigned g_done;            // zero-init; last evreduce block resets it

__device__ __constant__ int c_loff[4] = {0, 32768, 163840, 688128};

// ---------------------------------------------------------------------------
__device__ __forceinline__ void red4(float2* addr, float a, float b, float c, float d) {
    asm volatile("red.global.add.v4.f32 [%0], {%1,%2,%3,%4};" ::
                 "l"(addr), "f"(a), "f"(b), "f"(c), "f"(d) : "memory");
}
__device__ __forceinline__ void red2(float2* addr, float a, float b) {
    asm volatile("red.global.add.v2.f32 [%0], {%1,%2};" ::
                 "l"(addr), "f"(a), "f"(b) : "memory");
}
__device__ __forceinline__ float rsqrt_approx(float x) {
    float r;
    asm("rsqrt.approx.f32 %0, %1;" : "=f"(r) : "f"(x));
    return r;
}

// ---------------------------------------------------------------------------
__device__ __forceinline__ double block_reduce(float acc) {
    __shared__ double swarp[8];
    for (int o = 16; o > 0; o >>= 1) acc += __shfl_down_sync(0xffffffffu, acc, o);
    int wid = threadIdx.x >> 5, lid = threadIdx.x & 31;
    if (lid == 0) swarp[wid] = (double)acc;
    __syncthreads();
    double s = 0.0;
    if (threadIdx.x == 0)
        for (int w = 0; w < 8; w++) s += swarp[w];
    return s;
}

// ---------------------------------------------------------------------------
// k_pre: flow interleave (blocks [0,PRE_FI)) + tref scans (last 4 blocks)
// ---------------------------------------------------------------------------
#define PRE_FI 128
#define PRE_TREF 4
__global__ void __launch_bounds__(256)
k_pre(const float* __restrict__ f0, const float* __restrict__ f1,
      const float* __restrict__ f2, const float* __restrict__ f3,
      const float* __restrict__ ts, const int* __restrict__ ps) {
    int bid = blockIdx.x, tid = threadIdx.x;
    if (bid < PRE_FI) {
        const float* fl[4] = {f0, f1, f2, f3};
        for (int i = bid * 256 + tid; i < FI_TOT; i += PRE_FI * 256) {
            int l = (i < 8192) ? 0 : (i < 40960) ? 1 : (i < 172032) ? 2 : 3;
            int rem = i - c_fioff[l];
            int lg = 10 + 2 * l;
            int HW = 1 << lg;
            int b = rem >> lg;
            int p = rem & (HW - 1);
            const float* src = fl[l] + (size_t)b * 2 * HW;
            g_fint[i] = make_float2(src[p], src[p + HW]);
        }
    } else {
        int w = (bid - PRE_FI) * 8 + (tid >> 5);  // 0..31
        int lane = tid & 31;
        int b = w >> 2, m = (w >> 1) & 1, which = w & 1;
        int want = m ? -1 : 1;
        const int* pp = ps + b * NEV;
        const float* tt = ts + b * NEV;
        if (which == 0) {       // first matching (backward t_ref)
            bool found = false;
            for (int base = 0; base < NEV && !found; base += 32) {
                int idx = base + lane;
                bool hit = (idx < NEV) && (pp[idx] == want);
                unsigned bal = __ballot_sync(0xffffffffu, hit);
                if (bal) {
                    if (lane == 0) g_tref[b][m][0] = tt[base + __ffs(bal) - 1];
                    found = true;
                }
            }
            if (!found && lane == 0) g_tref[b][m][0] = tt[0];
        } else {                // last matching (forward t_ref)
            bool found = false;
            for (int base = NEV - 1; base >= 0 && !found; base -= 32) {
                int idx = base - lane;
                bool hit = (idx >= 0) && (pp[idx] == want);
                unsigned bal = __ballot_sync(0xffffffffu, hit);
                if (bal) {
                    if (lane == 0) g_tref[b][m][1] = tt[base - (__ffs(bal) - 1)];
                    found = true;
                }
            }
            if (!found && lane == 0) g_tref[b][m][1] = tt[NEV - 1];
        }
    }
}

// ---------------------------------------------------------------------------
// Bilinear scatter: even x0 -> one v4 per row; odd x0 -> two v2 per row.
// ---------------------------------------------------------------------------
__device__ __forceinline__ void scatter(float2* __restrict__ img, int W,
                                        float xl, float yl, float t_,
                                        float fx, float fy, float t) {
    float xf = fminf(fmaxf(fmaf(t_, fx, xl), 0.f), (float)(W - 1));
    float yf = fminf(fmaxf(fmaf(t_, fy, yl), 0.f), (float)(W - 1));
    float x0 = floorf(xf), y0 = floorf(yf);
    float x0w = xf - x0, y0w = yf - y0;
    float x1w = 1.f - x0w, y1w = 1.f - y0w;
    int x0i = (int)x0, y0i = (int)y0;
    int y1i = min(y0i + 1, W - 1);
    float nA = x1w * t;
    float nB = x0w * t;
    if (!(x0i & 1)) {
        red4(img + (y0i * W + x0i), nA * y1w, 1.f, nB * y1w, 1.f);
        red4(img + (y1i * W + x0i), nA * y0w, 1.f, nB * y0w, 1.f);
    } else {
        int x1i = min(x0i + 1, W - 1);
        red2(img + (y0i * W + x0i), nA * y1w, 1.f);
        red2(img + (y0i * W + x1i), nB * y1w, 1.f);
        red2(img + (y1i * W + x0i), nA * y0w, 1.f);
        red2(img + (y1i * W + x1i), nB * y0w, 1.f);
    }
}

// ---------------------------------------------------------------------------
// k_main roles: [0,NB_SM) smoothness | [NB_SM,+NB_WD) weight decay | rest events
// ---------------------------------------------------------------------------
#define NB_EV 3125
__device__ __constant__ int c_smb[5] = {0, 384, 480, 504, 512};

__global__ void __launch_bounds__(256)
k_main(const float* __restrict__ f0, const float* __restrict__ f1,
       const float* __restrict__ f2, const float* __restrict__ f3,
       const int* __restrict__ xs, const int* __restrict__ ys,
       const float* __restrict__ ts, const int* __restrict__ ps,
       const float* __restrict__ params) {
    int tid = threadIdx.x;
    if (blockIdx.x < NB_SM) {
        int l, b0, b1;
        if (blockIdx.x < c_smb[1])      { l = 3; b0 = c_smb[0]; b1 = c_smb[1]; }
        else if (blockIdx.x < c_smb[2]) { l = 2; b0 = c_smb[1]; b1 = c_smb[2]; }
        else if (blockIdx.x < c_smb[3]) { l = 1; b0 = c_smb[2]; b1 = c_smb[3]; }
        else                            { l = 0; b0 = c_smb[3]; b1 = c_smb[4]; }
        const float* f = (l == 3) ? f3 : (l == 2) ? f2 : (l == 1) ? f1 : f0;
        const int W = 32 << l;
        const int HW = W * W;
        const int n = 16 * HW;
        float inv_lr = 1.f / (16.f * W * (W - 1));
        float inv_d  = 1.f / (16.f * (W - 1) * (W - 1));
        int stride = (b1 - b0) * 256;
        float acc = 0.f;
        for (int i = (blockIdx.x - b0) * 256 + tid; i < n; i += stride) {
            int pix = i & (HW - 1);
            int col = pix & (W - 1);
            int row = pix >> (5 + l);
            float v = f[i];
            bool hr = (col < W - 1), hd = (row < W - 1);
            if (hr) {
                float r = f[i + 1];
                float d1 = r - v;
                acc += __powf(d1 * d1 + 1e-6f, 0.45f) * inv_lr;
                if (hd) {
                    float dn = f[i + W];
                    float dr = f[i + W + 1];
                    float t1 = dr - v;
                    float t2 = r - dn;
                    acc += (__powf(t1 * t1 + 1e-6f, 0.45f) +
                            __powf(t2 * t2 + 1e-6f, 0.45f)) * inv_d;
                }
            }
            if (hd) {
                float dn = f[i + W];
                float d2 = dn - v;
                acc += __powf(d2 * d2 + 1e-6f, 0.45f) * inv_lr;
            }
        }
        double s = block_reduce(acc);
        if (tid == 0) g_part_sm[blockIdx.x] = s;
    } else if (blockIdx.x < NB_SM + NB_WD) {
        const float4* p4 = (const float4*)params;
        float acc = 0.f;
        for (int i = (blockIdx.x - NB_SM) * 256 + tid; i < NPARAMS / 4; i += NB_WD * 256) {
            float4 v = p4[i];
            acc += v.x * v.x + v.y * v.y + v.z * v.z + v.w * v.w;
        }
        double s = block_reduce(acc);
        if (tid == 0) g_part_wd[blockIdx.x - NB_SM] = s;
    } else {
        int idx = (blockIdx.x - NB_SM - NB_WD) * 256 + tid;
        if (idx >= B * NEV) return;
        int b = idx / NEV;
        int x = xs[idx], y = ys[idx];
        float t = ts[idx];
        int m = (ps[idx] == 1) ? 0 : 1;
        float tfw = g_tref[b][m][1] - t + EPSF;
        float tbw = g_tref[b][m][0] - t - EPSF;
#pragma unroll
        for (int l = 0; l < 4; l++) {
            const int W = 32 << l;
            const int HW = W * W;
            int xl = x >> (3 - l), yl = y >> (3 - l);
            float2 fv = __ldg(g_fint + c_fioff[l] + b * HW + yl * W + xl);
            float2* base = g_accum + c_loff[l];
            scatter(base + (size_t)((b * 2 + 1) * 2 + m) * HW, W,
                    (float)xl, (float)yl, tfw, fv.x, fv.y, t);
            scatter(base + (size_t)((b * 2 + 0) * 2 + m) * HW, W,
                    (float)xl, (float)yl, tbw, fv.x, fv.y, t);
        }
    }
}

// ---------------------------------------------------------------------------
// k_evreduce: sqrt((num/den')^2+1e-6) = h*rsqrt(h*den'^2), h=num^2+1e-6*den'^2.
// Restores zeros to g_accum for the next replay; last block emits final sum.
// ---------------------------------------------------------------------------
__global__ void __launch_bounds__(256) k_evreduce(float* __restrict__ out) {
    float4* acc4 = (float4*)g_accum;
    const int n4 = ACCUM_F2 / 2;
    int stride = NB_ER * 256;
    float acc = 0.f;
    const float4 z = make_float4(0.f, 0.f, 0.f, 0.f);
    for (int i = blockIdx.x * 256 + threadIdx.x; i < n4; i += stride) {
        float4 v = acc4[i];
        acc4[i] = z;
        float d0 = v.y + EPSF, d1 = v.w + EPSF;
        float d0s = d0 * d0,   d1s = d1 * d1;
        float h0 = fmaf(v.x, v.x, 1e-6f * d0s);
        float h1 = fmaf(v.z, v.z, 1e-6f * d1s);
        acc += h0 * rsqrt_approx(h0 * d0s) + h1 * rsqrt_approx(h1 * d1s);
    }
    double s = block_reduce(acc);
    __shared__ bool is_last;
    if (threadIdx.x == 0) {
        g_part_er[blockIdx.x] = s;
        __threadfence();
        unsigned r = atomicAdd(&g_done, 1u);
        is_last = (r == NB_ER - 1);
    }
    __syncthreads();
    if (is_last) {
        __shared__ double swarp[8];
        double tot = 0.0;
        for (int i = threadIdx.x; i < NB_ER; i += 256) tot += g_part_er[i];
        for (int i = threadIdx.x; i < NB_SM; i += 256) tot += 6.25 * g_part_sm[i];
        for (int i = threadIdx.x; i < NB_WD; i += 256) tot += 5.0e-5 * g_part_wd[i];
        for (int o = 16; o > 0; o >>= 1) tot += __shfl_down_sync(0xffffffffu, tot, o);
        if ((threadIdx.x & 31) == 0) swarp[threadIdx.x >> 5] = tot;
        __syncthreads();
        if (threadIdx.x == 0) {
            double r = 0.0;
            for (int w = 0; w < 8; w++) r += swarp[w];
            out[0] = (float)r;
            g_done = 0;          // reset for next graph replay
        }
    }
}

// ---------------------------------------------------------------------------
extern "C" void kernel_launch(void* const* d_in, const int* in_sizes, int n_in,
                              void* d_out, int out_size) {
    const float* f0 = (const float*)d_in[0];
    const float* f1 = (const float*)d_in[1];
    const float* f2 = (const float*)d_in[2];
    const float* f3 = (const float*)d_in[3];
    const int*   xs = (const int*)d_in[4];
    const int*   ys = (const int*)d_in[5];
    const float* ts = (const float*)d_in[6];
    const int*   ps = (const int*)d_in[7];
    const float* params = (const float*)d_in[10];
    float* out = (float*)d_out;

    k_pre<<<PRE_FI + PRE_TREF, 256>>>(f0, f1, f2, f3, ts, ps);
    k_main<<<NB_SM + NB_WD + NB_EV, 256>>>(f0, f1, f2, f3, xs, ys, ts, ps, params);
    k_evreduce<<<NB_ER, 256>>>(out);
}

// round 6
// speedup vs baseline: 1.0125x; 1.0125x over previous
#include <cuda_runtime.h>
#include <math.h>

#define B 8
#define NEV 100000
#define NPARAMS 4000000
#define EPSF 1.1920928955078125e-07f

// Accumulator: float2 per pixel (x=num, y=den), 16B-aligned for v4 REDs.
// Zero at module load; k_evreduce restores zeros after reading (validated R5).
#define ACCUM_F2 2785280
__device__ __align__(16) float2 g_accum[ACCUM_F2];
__device__ float g_tref[B][2][2];       // [b][m][0]=first(bwd), [1]=last(fwd)

#define NB_SM 512
#define NB_WD 384
#define NB_ER 1024
__device__ double g_part_sm[NB_SM];
__device__ double g_part_wd[NB_WD];
__device__ double g_part_er[NB_ER];
__device__ unsigned g_done;            // zero-init; last evreduce block resets it

__device__ __constant__ int c_loff[4] = {0, 32768, 163840, 688128};

// ---------------------------------------------------------------------------
__device__ __forceinline__ void red4(float2* addr, float a, float b, float c, float d) {
    asm volatile("red.global.add.v4.f32 [%0], {%1,%2,%3,%4};" ::
                 "l"(addr), "f"(a), "f"(b), "f"(c), "f"(d) : "memory");
}
__device__ __forceinline__ void red2(float2* addr, float a, float b) {
    asm volatile("red.global.add.v2.f32 [%0], {%1,%2};" ::
                 "l"(addr), "f"(a), "f"(b) : "memory");
}
__device__ __forceinline__ float rsqrt_approx(float x) {
    float r;
    asm("rsqrt.approx.f32 %0, %1;" : "=f"(r) : "f"(x));
    return r;
}

// ---------------------------------------------------------------------------
__device__ __forceinline__ double block_reduce(float acc) {
    __shared__ double swarp[8];
    for (int o = 16; o > 0; o >>= 1) acc += __shfl_down_sync(0xffffffffu, acc, o);
    int wid = threadIdx.x >> 5, lid = threadIdx.x & 31;
    if (lid == 0) swarp[wid] = (double)acc;
    __syncthreads();
    double s = 0.0;
    if (threadIdx.x == 0)
        for (int w = 0; w < 8; w++) s += swarp[w];
    return s;
}

// ---------------------------------------------------------------------------
// k_pre: weight decay (blocks [0,NB_WD)) + tref scans (last 4 blocks)
// ---------------------------------------------------------------------------
#define PRE_TREF 4
__global__ void __launch_bounds__(256)
k_pre(const float* __restrict__ params,
      const float* __restrict__ ts, const int* __restrict__ ps) {
    int bid = blockIdx.x, tid = threadIdx.x;
    if (bid < NB_WD) {
        const float4* p4 = (const float4*)params;
        float acc = 0.f;
        for (int i = bid * 256 + tid; i < NPARAMS / 4; i += NB_WD * 256) {
            float4 v = p4[i];
            acc += v.x * v.x + v.y * v.y + v.z * v.z + v.w * v.w;
        }
        double s = block_reduce(acc);
        if (tid == 0) g_part_wd[bid] = s;
    } else {
        int w = (bid - NB_WD) * 8 + (tid >> 5);  // 0..31
        int lane = tid & 31;
        int b = w >> 2, m = (w >> 1) & 1, which = w & 1;
        int want = m ? -1 : 1;
        const int* pp = ps + b * NEV;
        const float* tt = ts + b * NEV;
        if (which == 0) {       // first matching (backward t_ref)
            bool found = false;
            for (int base = 0; base < NEV && !found; base += 32) {
                int idx = base + lane;
                bool hit = (idx < NEV) && (pp[idx] == want);
                unsigned bal = __ballot_sync(0xffffffffu, hit);
                if (bal) {
                    if (lane == 0) g_tref[b][m][0] = tt[base + __ffs(bal) - 1];
                    found = true;
                }
            }
            if (!found && lane == 0) g_tref[b][m][0] = tt[0];
        } else {                // last matching (forward t_ref)
            bool found = false;
            for (int base = NEV - 1; base >= 0 && !found; base -= 32) {
                int idx = base - lane;
                bool hit = (idx >= 0) && (pp[idx] == want);
                unsigned bal = __ballot_sync(0xffffffffu, hit);
                if (bal) {
                    if (lane == 0) g_tref[b][m][1] = tt[base - (__ffs(bal) - 1)];
                    found = true;
                }
            }
            if (!found && lane == 0) g_tref[b][m][1] = tt[NEV - 1];
        }
    }
}

// ---------------------------------------------------------------------------
// Bilinear scatter: even x0 -> one v4 per row; odd x0 -> two v2 per row.
// ---------------------------------------------------------------------------
__device__ __forceinline__ void scatter(float2* __restrict__ img, int W,
                                        float xl, float yl, float t_,
                                        float fx, float fy, float t) {
    float xf = fminf(fmaxf(fmaf(t_, fx, xl), 0.f), (float)(W - 1));
    float yf = fminf(fmaxf(fmaf(t_, fy, yl), 0.f), (float)(W - 1));
    float x0 = floorf(xf), y0 = floorf(yf);
    float x0w = xf - x0, y0w = yf - y0;
    float x1w = 1.f - x0w, y1w = 1.f - y0w;
    int x0i = (int)x0, y0i = (int)y0;
    int y1i = min(y0i + 1, W - 1);
    float nA = x1w * t;
    float nB = x0w * t;
    if (!(x0i & 1)) {
        red4(img + (y0i * W + x0i), nA * y1w, 1.f, nB * y1w, 1.f);
        red4(img + (y1i * W + x0i), nA * y0w, 1.f, nB * y0w, 1.f);
    } else {
        int x1i = min(x0i + 1, W - 1);
        red2(img + (y0i * W + x0i), nA * y1w, 1.f);
        red2(img + (y0i * W + x1i), nB * y1w, 1.f);
        red2(img + (y1i * W + x0i), nA * y0w, 1.f);
        red2(img + (y1i * W + x1i), nB * y0w, 1.f);
    }
}

// ---------------------------------------------------------------------------
// k_main roles: [0,NB_SM) smoothness | rest events
// ---------------------------------------------------------------------------
#define NB_EV 3125
__device__ __constant__ int c_smb[5] = {0, 384, 480, 504, 512};

__global__ void __launch_bounds__(256)
k_main(const float* __restrict__ f0, const float* __restrict__ f1,
       const float* __restrict__ f2, const float* __restrict__ f3,
       const int* __restrict__ xs, const int* __restrict__ ys,
       const float* __restrict__ ts, const int* __restrict__ ps) {
    int tid = threadIdx.x;
    if (blockIdx.x < NB_SM) {
        int l, b0, b1;
        if (blockIdx.x < c_smb[1])      { l = 3; b0 = c_smb[0]; b1 = c_smb[1]; }
        else if (blockIdx.x < c_smb[2]) { l = 2; b0 = c_smb[1]; b1 = c_smb[2]; }
        else if (blockIdx.x < c_smb[3]) { l = 1; b0 = c_smb[2]; b1 = c_smb[3]; }
        else                            { l = 0; b0 = c_smb[3]; b1 = c_smb[4]; }
        const float* f = (l == 3) ? f3 : (l == 2) ? f2 : (l == 1) ? f1 : f0;
        const int W = 32 << l;
        const int HW = W * W;
        const int n = 16 * HW;
        float inv_lr = 1.f / (16.f * W * (W - 1));
        float inv_d  = 1.f / (16.f * (W - 1) * (W - 1));
        int stride = (b1 - b0) * 256;
        float acc = 0.f;
        for (int i = (blockIdx.x - b0) * 256 + tid; i < n; i += stride) {
            int pix = i & (HW - 1);
            int col = pix & (W - 1);
            int row = pix >> (5 + l);
            float v = f[i];
            bool hr = (col < W - 1), hd = (row < W - 1);
            if (hr) {
                float r = f[i + 1];
                float d1 = r - v;
                acc += __powf(d1 * d1 + 1e-6f, 0.45f) * inv_lr;
                if (hd) {
                    float dn = f[i + W];
                    float dr = f[i + W + 1];
                    float t1 = dr - v;
                    float t2 = r - dn;
                    acc += (__powf(t1 * t1 + 1e-6f, 0.45f) +
                            __powf(t2 * t2 + 1e-6f, 0.45f)) * inv_d;
                }
            }
            if (hd) {
                float dn = f[i + W];
                float d2 = dn - v;
                acc += __powf(d2 * d2 + 1e-6f, 0.45f) * inv_lr;
            }
        }
        double s = block_reduce(acc);
        if (tid == 0) g_part_sm[blockIdx.x] = s;
    } else {
        int idx = (blockIdx.x - NB_SM) * 256 + tid;
        if (idx >= B * NEV) return;
        int b = idx / NEV;
        int x = xs[idx], y = ys[idx];
        float t = ts[idx];
        int m = (ps[idx] == 1) ? 0 : 1;
        float tfw = g_tref[b][m][1] - t + EPSF;
        float tbw = g_tref[b][m][0] - t - EPSF;
        const float* fl[4] = {f0, f1, f2, f3};
#pragma unroll
        for (int l = 0; l < 4; l++) {
            const int W = 32 << l;
            const int HW = W * W;
            int xl = x >> (3 - l), yl = y >> (3 - l);
            const float* fp = fl[l] + (size_t)b * 2 * HW + yl * W + xl;
            float fx = __ldg(fp);
            float fy = __ldg(fp + HW);
            float2* base = g_accum + c_loff[l];
            scatter(base + (size_t)((b * 2 + 1) * 2 + m) * HW, W,
                    (float)xl, (float)yl, tfw, fx, fy, t);
            scatter(base + (size_t)((b * 2 + 0) * 2 + m) * HW, W,
                    (float)xl, (float)yl, tbw, fx, fy, t);
        }
    }
}

// ---------------------------------------------------------------------------
// k_evreduce: sqrt((num/den')^2+1e-6) = h*rsqrt(h*den'^2), h=num^2+1e-6*den'^2.
// Restores zeros to g_accum for the next replay; last block emits final sum.
// ---------------------------------------------------------------------------
__global__ void __launch_bounds__(256) k_evreduce(float* __restrict__ out) {
    float4* acc4 = (float4*)g_accum;
    const int n4 = ACCUM_F2 / 2;
    int stride = NB_ER * 256;
    float acc = 0.f;
    const float4 z = make_float4(0.f, 0.f, 0.f, 0.f);
    for (int i = blockIdx.x * 256 + threadIdx.x; i < n4; i += stride) {
        float4 v = acc4[i];
        acc4[i] = z;
        float d0 = v.y + EPSF, d1 = v.w + EPSF;
        float d0s = d0 * d0,   d1s = d1 * d1;
        float h0 = fmaf(v.x, v.x, 1e-6f * d0s);
        float h1 = fmaf(v.z, v.z, 1e-6f * d1s);
        acc += h0 * rsqrt_approx(h0 * d0s) + h1 * rsqrt_approx(h1 * d1s);
    }
    double s = block_reduce(acc);
    __shared__ bool is_last;
    if (threadIdx.x == 0) {
        g_part_er[blockIdx.x] = s;
        __threadfence();
        unsigned r = atomicAdd(&g_done, 1u);
        is_last = (r == NB_ER - 1);
    }
    __syncthreads();
    if (is_last) {
        __shared__ double swarp[8];
        double tot = 0.0;
        for (int i = threadIdx.x; i < NB_ER; i += 256) tot += g_part_er[i];
        for (int i = threadIdx.x; i < NB_SM; i += 256) tot += 6.25 * g_part_sm[i];
        for (int i = threadIdx.x; i < NB_WD; i += 256) tot += 5.0e-5 * g_part_wd[i];
        for (int o = 16; o > 0; o >>= 1) tot += __shfl_down_sync(0xffffffffu, tot, o);
        if ((threadIdx.x & 31) == 0) swarp[threadIdx.x >> 5] = tot;
        __syncthreads();
        if (threadIdx.x == 0) {
            double r = 0.0;
            for (int w = 0; w < 8; w++) r += swarp[w];
            out[0] = (float)r;
            g_done = 0;          // reset for next graph replay
        }
    }
}

// ---------------------------------------------------------------------------
extern "C" void kernel_launch(void* const* d_in, const int* in_sizes, int n_in,
                              void* d_out, int out_size) {
    const float* f0 = (const float*)d_in[0];
    const float* f1 = (const float*)d_in[1];
    const float* f2 = (const float*)d_in[2];
    const float* f3 = (const float*)d_in[3];
    const int*   xs = (const int*)d_in[4];
    const int*   ys = (const int*)d_in[5];
    const float* ts = (const float*)d_in[6];
    const int*   ps = (const int*)d_in[7];
    const float* params = (const float*)d_in[10];
    float* out = (float*)d_out;

    k_pre<<<NB_WD + PRE_TREF, 256>>>(params, ts, ps);
    k_main<<<NB_SM + NB_EV, 256>>>(f0, f1, f2, f3, xs, ys, ts, ps);
    k_evreduce<<<NB_ER, 256>>>(out);
}

// round 7
// speedup vs baseline: 1.1113x; 1.0976x over previous
#include <cuda_runtime.h>
#include <math.h>

#define B 8
#define NEV 100000
#define NPARAMS 4000000
#define EPSF 1.1920928955078125e-07f

// Accumulator: float2 per pixel (x=num, y=den), 16B-aligned for v4 REDs.
#define ACCUM_F2 2785280
__device__ __align__(16) float2 g_accum[ACCUM_F2];
__device__ float g_tref[B][2][2];       // [b][m][0]=first(bwd), [1]=last(fwd)

#define NB_SM 512
#define NB_WD 256
#define NB_ER 1024
__device__ double g_part_sm[NB_SM];
__device__ double g_part_wd[NB_WD];
__device__ double g_part_er[NB_ER];
__device__ unsigned g_done;

__device__ __constant__ int c_loff[4] = {0, 32768, 163840, 688128};

// ---------------------------------------------------------------------------
__device__ __forceinline__ void red4(float2* addr, float a, float b, float c, float d) {
    asm volatile("red.global.add.v4.f32 [%0], {%1,%2,%3,%4};" ::
                 "l"(addr), "f"(a), "f"(b), "f"(c), "f"(d) : "memory");
}
__device__ __forceinline__ void red2(float2* addr, float a, float b) {
    asm volatile("red.global.add.v2.f32 [%0], {%1,%2};" ::
                 "l"(addr), "f"(a), "f"(b) : "memory");
}
__device__ __forceinline__ float rsqrt_approx(float x) {
    float r;
    asm("rsqrt.approx.f32 %0, %1;" : "=f"(r) : "f"(x));
    return r;
}

// ---------------------------------------------------------------------------
__device__ __forceinline__ double block_reduce(float acc) {
    __shared__ double swarp[8];
    for (int o = 16; o > 0; o >>= 1) acc += __shfl_down_sync(0xffffffffu, acc, o);
    int wid = threadIdx.x >> 5, lid = threadIdx.x & 31;
    if (lid == 0) swarp[wid] = (double)acc;
    __syncthreads();
    double s = 0.0;
    if (threadIdx.x == 0)
        for (int w = 0; w < 8; w++) s += swarp[w];
    return s;
}

// ---------------------------------------------------------------------------
// k_pre: zero accum + counter | weight decay | tref scans   (R4 structure)
// ---------------------------------------------------------------------------
#define PRE_ZERO 512
#define PRE_WD   NB_WD
#define PRE_TREF 4
__global__ void __launch_bounds__(256)
k_pre(const float* __restrict__ ts, const int* __restrict__ ps,
      const float* __restrict__ params) {
    int bid = blockIdx.x, tid = threadIdx.x;
    if (bid < PRE_ZERO) {
        if (bid == 0 && tid == 0) g_done = 0;
        float4* p = (float4*)g_accum;
        const int n = ACCUM_F2 / 2;
        for (int i = bid * 256 + tid; i < n; i += PRE_ZERO * 256)
            p[i] = make_float4(0.f, 0.f, 0.f, 0.f);
    } else if (bid < PRE_ZERO + PRE_WD) {
        const float4* p4 = (const float4*)params;
        float acc = 0.f;
        for (int i = (bid - PRE_ZERO) * 256 + tid; i < NPARAMS / 4; i += PRE_WD * 256) {
            float4 v = p4[i];
            acc += v.x * v.x + v.y * v.y + v.z * v.z + v.w * v.w;
        }
        double s = block_reduce(acc);
        if (tid == 0) g_part_wd[bid - PRE_ZERO] = s;
    } else {
        int w = (bid - (PRE_ZERO + PRE_WD)) * 8 + (tid >> 5);  // 0..31
        int lane = tid & 31;
        int b = w >> 2, m = (w >> 1) & 1, which = w & 1;
        int want = m ? -1 : 1;
        const int* pp = ps + b * NEV;
        const float* tt = ts + b * NEV;
        if (which == 0) {       // first matching (backward t_ref)
            bool found = false;
            for (int base = 0; base < NEV && !found; base += 32) {
                int idx = base + lane;
                bool hit = (idx < NEV) && (pp[idx] == want);
                unsigned bal = __ballot_sync(0xffffffffu, hit);
                if (bal) {
                    if (lane == 0) g_tref[b][m][0] = tt[base + __ffs(bal) - 1];
                    found = true;
                }
            }
            if (!found && lane == 0) g_tref[b][m][0] = tt[0];
        } else {                // last matching (forward t_ref)
            bool found = false;
            for (int base = NEV - 1; base >= 0 && !found; base -= 32) {
                int idx = base - lane;
                bool hit = (idx >= 0) && (pp[idx] == want);
                unsigned bal = __ballot_sync(0xffffffffu, hit);
                if (bal) {
                    if (lane == 0) g_tref[b][m][1] = tt[base - (__ffs(bal) - 1)];
                    found = true;
                }
            }
            if (!found && lane == 0) g_tref[b][m][1] = tt[NEV - 1];
        }
    }
}

// ---------------------------------------------------------------------------
// Bilinear scatter: even x0 -> one v4 per row; odd x0 -> two v2 per row.
// ---------------------------------------------------------------------------
__device__ __forceinline__ void scatter(float2* __restrict__ img, int W,
                                        float xl, float yl, float t_,
                                        float fx, float fy, float t) {
    float xf = fminf(fmaxf(fmaf(t_, fx, xl), 0.f), (float)(W - 1));
    float yf = fminf(fmaxf(fmaf(t_, fy, yl), 0.f), (float)(W - 1));
    float x0 = floorf(xf), y0 = floorf(yf);
    float x0w = xf - x0, y0w = yf - y0;
    float x1w = 1.f - x0w, y1w = 1.f - y0w;
    int x0i = (int)x0, y0i = (int)y0;
    int y1i = min(y0i + 1, W - 1);
    float nA = x1w * t;
    float nB = x0w * t;
    if (!(x0i & 1)) {
        red4(img + (y0i * W + x0i), nA * y1w, 1.f, nB * y1w, 1.f);
        red4(img + (y1i * W + x0i), nA * y0w, 1.f, nB * y0w, 1.f);
    } else {
        int x1i = min(x0i + 1, W - 1);
        red2(img + (y0i * W + x0i), nA * y1w, 1.f);
        red2(img + (y0i * W + x1i), nB * y1w, 1.f);
        red2(img + (y1i * W + x0i), nA * y0w, 1.f);
        red2(img + (y1i * W + x1i), nB * y0w, 1.f);
    }
}

// ---------------------------------------------------------------------------
// k_main roles: [0,NB_SM) smoothness | rest events   (identical to R4)
// ---------------------------------------------------------------------------
#define NB_EV 3125
__device__ __constant__ int c_smb[5] = {0, 384, 480, 504, 512};

__global__ void __launch_bounds__(256)
k_main(const float* __restrict__ f0, const float* __restrict__ f1,
       const float* __restrict__ f2, const float* __restrict__ f3,
       const int* __restrict__ xs, const int* __restrict__ ys,
       const float* __restrict__ ts, const int* __restrict__ ps) {
    int tid = threadIdx.x;
    if (blockIdx.x < NB_SM) {
        int l, b0, b1;
        if (blockIdx.x < c_smb[1])      { l = 3; b0 = c_smb[0]; b1 = c_smb[1]; }
        else if (blockIdx.x < c_smb[2]) { l = 2; b0 = c_smb[1]; b1 = c_smb[2]; }
        else if (blockIdx.x < c_smb[3]) { l = 1; b0 = c_smb[2]; b1 = c_smb[3]; }
        else                            { l = 0; b0 = c_smb[3]; b1 = c_smb[4]; }
        const float* f = (l == 3) ? f3 : (l == 2) ? f2 : (l == 1) ? f1 : f0;
        const int W = 32 << l;
        const int HW = W * W;
        const int n = 16 * HW;
        float inv_lr = 1.f / (16.f * W * (W - 1));
        float inv_d  = 1.f / (16.f * (W - 1) * (W - 1));
        int stride = (b1 - b0) * 256;
        float acc = 0.f;
        for (int i = (blockIdx.x - b0) * 256 + tid; i < n; i += stride) {
            int pix = i & (HW - 1);
            int col = pix & (W - 1);
            int row = pix >> (5 + l);
            float v = f[i];
            bool hr = (col < W - 1), hd = (row < W - 1);
            if (hr) {
                float r = f[i + 1];
                float d1 = r - v;
                acc += __powf(d1 * d1 + 1e-6f, 0.45f) * inv_lr;
                if (hd) {
                    float dn = f[i + W];
                    float dr = f[i + W + 1];
                    float t1 = dr - v;
                    float t2 = r - dn;
                    acc += (__powf(t1 * t1 + 1e-6f, 0.45f) +
                            __powf(t2 * t2 + 1e-6f, 0.45f)) * inv_d;
                }
            }
            if (hd) {
                float dn = f[i + W];
                float d2 = dn - v;
                acc += __powf(d2 * d2 + 1e-6f, 0.45f) * inv_lr;
            }
        }
        double s = block_reduce(acc);
        if (tid == 0) g_part_sm[blockIdx.x] = s;
    } else {
        int idx = (blockIdx.x - NB_SM) * 256 + tid;
        if (idx >= B * NEV) return;
        int b = idx / NEV;
        int x = xs[idx], y = ys[idx];
        float t = ts[idx];
        int m = (ps[idx] == 1) ? 0 : 1;
        float tfw = g_tref[b][m][1] - t + EPSF;
        float tbw = g_tref[b][m][0] - t - EPSF;
        const float* fl[4] = {f0, f1, f2, f3};
#pragma unroll
        for (int l = 0; l < 4; l++) {
            const int W = 32 << l;
            const int HW = W * W;
            int xl = x >> (3 - l), yl = y >> (3 - l);
            const float* fp = fl[l] + (size_t)b * 2 * HW + yl * W + xl;
            float fx = __ldg(fp);
            float fy = __ldg(fp + HW);
            float2* base = g_accum + c_loff[l];
            scatter(base + (size_t)((b * 2 + 1) * 2 + m) * HW, W,
                    (float)xl, (float)yl, tfw, fx, fy, t);
            scatter(base + (size_t)((b * 2 + 0) * 2 + m) * HW, W,
                    (float)xl, (float)yl, tbw, fx, fy, t);
        }
    }
}

// ---------------------------------------------------------------------------
// k_evreduce: pure read; sqrt((n/d')^2+1e-6) = h*rsqrt(h*d'^2), h=n^2+1e-6*d'^2.
// Last block folds in smoothness/WD partials and writes the scalar result.
// ---------------------------------------------------------------------------
__global__ void __launch_bounds__(256) k_evreduce(float* __restrict__ out) {
    const float4* acc4 = (const float4*)g_accum;
    const int n4 = ACCUM_F2 / 2;
    int stride = NB_ER * 256;
    float acc = 0.f;
    for (int i = blockIdx.x * 256 + threadIdx.x; i < n4; i += stride) {
        float4 v = acc4[i];
        float d0 = v.y + EPSF, d1 = v.w + EPSF;
        float d0s = d0 * d0,   d1s = d1 * d1;
        float h0 = fmaf(v.x, v.x, 1e-6f * d0s);
        float h1 = fmaf(v.z, v.z, 1e-6f * d1s);
        acc += h0 * rsqrt_approx(h0 * d0s) + h1 * rsqrt_approx(h1 * d1s);
    }
    double s = block_reduce(acc);
    __shared__ bool is_last;
    if (threadIdx.x == 0) {
        g_part_er[blockIdx.x] = s;
        __threadfence();
        unsigned r = atomicAdd(&g_done, 1u);
        is_last = (r == NB_ER - 1);
    }
    __syncthreads();
    if (is_last) {
        __shared__ double swarp[8];
        double tot = 0.0;
        for (int i = threadIdx.x; i < NB_ER; i += 256) tot += g_part_er[i];
        for (int i = threadIdx.x; i < NB_SM; i += 256) tot += 6.25 * g_part_sm[i];
        for (int i = threadIdx.x; i < NB_WD; i += 256) tot += 5.0e-5 * g_part_wd[i];
        for (int o = 16; o > 0; o >>= 1) tot += __shfl_down_sync(0xffffffffu, tot, o);
        if ((threadIdx.x & 31) == 0) swarp[threadIdx.x >> 5] = tot;
        __syncthreads();
        if (threadIdx.x == 0) {
            double r = 0.0;
            for (int w = 0; w < 8; w++) r += swarp[w];
            out[0] = (float)r;
        }
    }
}

// ---------------------------------------------------------------------------
extern "C" void kernel_launch(void* const* d_in, const int* in_sizes, int n_in,
                              void* d_out, int out_size) {
    const float* f0 = (const float*)d_in[0];
    const float* f1 = (const float*)d_in[1];
    const float* f2 = (const float*)d_in[2];
    const float* f3 = (const float*)d_in[3];
    const int*   xs = (const int*)d_in[4];
    const int*   ys = (const int*)d_in[5];
    const float* ts = (const float*)d_in[6];
    const int*   ps = (const int*)d_in[7];
    const float* params = (const float*)d_in[10];
    float* out = (float*)d_out;

    k_pre<<<PRE_ZERO + PRE_WD + PRE_TREF, 256>>>(ts, ps, params);
    k_main<<<NB_SM + NB_EV, 256>>>(f0, f1, f2, f3, xs, ys, ts, ps);
    k_evreduce<<<NB_ER, 256>>>(out);
}

// round 8
// speedup vs baseline: 1.1232x; 1.0107x over previous
#include <cuda_runtime.h>
#include <math.h>

#define B 8
#define NEV 100000
#define NPARAMS 4000000
#define EPSF 1.1920928955078125e-07f

// Accumulator: float2 per pixel (x=num, y=den), 16B-aligned for v4 REDs.
#define ACCUM_F2 2785280
__device__ __align__(16) float2 g_accum[ACCUM_F2];
__device__ float g_tref[B][2][2];       // [b][m][0]=first(bwd), [1]=last(fwd)

#define NB_SM 512
#define NB_WD 256
#define NB_ER 1024
__device__ double g_part_sm[NB_SM];
__device__ double g_part_wd[NB_WD];
__device__ double g_part_er[NB_ER];
__device__ unsigned g_done;

__device__ __constant__ int c_loff[4] = {0, 32768, 163840, 688128};

// ---------------------------------------------------------------------------
__device__ __forceinline__ void red4(float2* addr, float a, float b, float c, float d) {
    asm volatile("red.global.add.v4.f32 [%0], {%1,%2,%3,%4};" ::
                 "l"(addr), "f"(a), "f"(b), "f"(c), "f"(d) : "memory");
}
__device__ __forceinline__ void red2(float2* addr, float a, float b) {
    asm volatile("red.global.add.v2.f32 [%0], {%1,%2};" ::
                 "l"(addr), "f"(a), "f"(b) : "memory");
}
__device__ __forceinline__ float rsqrt_approx(float x) {
    float r;
    asm("rsqrt.approx.f32 %0, %1;" : "=f"(r) : "f"(x));
    return r;
}

// ---------------------------------------------------------------------------
__device__ __forceinline__ double block_reduce(float acc) {
    __shared__ double swarp[8];
    for (int o = 16; o > 0; o >>= 1) acc += __shfl_down_sync(0xffffffffu, acc, o);
    int wid = threadIdx.x >> 5, lid = threadIdx.x & 31;
    if (lid == 0) swarp[wid] = (double)acc;
    __syncthreads();
    double s = 0.0;
    if (threadIdx.x == 0)
        for (int w = 0; w < 8; w++) s += swarp[w];
    return s;
}

// ---------------------------------------------------------------------------
// k_pre: zero accum + counter | weight decay (MLP-4 unrolled) | tref scans
// ---------------------------------------------------------------------------
#define PRE_ZERO 512
#define PRE_WD   NB_WD
#define PRE_TREF 4
__global__ void __launch_bounds__(256)
k_pre(const float* __restrict__ ts, const int* __restrict__ ps,
      const float* __restrict__ params) {
    int bid = blockIdx.x, tid = threadIdx.x;
    if (bid < PRE_ZERO) {
        if (bid == 0 && tid == 0) g_done = 0;
        float4* p = (float4*)g_accum;
        const int n = ACCUM_F2 / 2;
        for (int i = bid * 256 + tid; i < n; i += PRE_ZERO * 256)
            p[i] = make_float4(0.f, 0.f, 0.f, 0.f);
    } else if (bid < PRE_ZERO + PRE_WD) {
        const float4* p4 = (const float4*)params;
        const int n4 = NPARAMS / 4;
        float a0 = 0.f, a1 = 0.f, a2 = 0.f, a3 = 0.f;
        for (int base = (bid - PRE_ZERO) * 1024 + tid; base < n4; base += PRE_WD * 1024) {
            int i1 = base + 256, i2 = base + 512, i3 = base + 768;
            float4 v0 = p4[base];
            float4 v1 = (i1 < n4) ? p4[i1] : make_float4(0.f, 0.f, 0.f, 0.f);
            float4 v2 = (i2 < n4) ? p4[i2] : make_float4(0.f, 0.f, 0.f, 0.f);
            float4 v3 = (i3 < n4) ? p4[i3] : make_float4(0.f, 0.f, 0.f, 0.f);
            a0 += v0.x * v0.x + v0.y * v0.y + v0.z * v0.z + v0.w * v0.w;
            a1 += v1.x * v1.x + v1.y * v1.y + v1.z * v1.z + v1.w * v1.w;
            a2 += v2.x * v2.x + v2.y * v2.y + v2.z * v2.z + v2.w * v2.w;
            a3 += v3.x * v3.x + v3.y * v3.y + v3.z * v3.z + v3.w * v3.w;
        }
        double s = block_reduce((a0 + a1) + (a2 + a3));
        if (tid == 0) g_part_wd[bid - PRE_ZERO] = s;
    } else {
        int w = (bid - (PRE_ZERO + PRE_WD)) * 8 + (tid >> 5);  // 0..31
        int lane = tid & 31;
        int b = w >> 2, m = (w >> 1) & 1, which = w & 1;
        int want = m ? -1 : 1;
        const int* pp = ps + b * NEV;
        const float* tt = ts + b * NEV;
        if (which == 0) {       // first matching (backward t_ref)
            bool found = false;
            for (int base = 0; base < NEV && !found; base += 32) {
                int idx = base + lane;
                bool hit = (idx < NEV) && (pp[idx] == want);
                unsigned bal = __ballot_sync(0xffffffffu, hit);
                if (bal) {
                    if (lane == 0) g_tref[b][m][0] = tt[base + __ffs(bal) - 1];
                    found = true;
                }
            }
            if (!found && lane == 0) g_tref[b][m][0] = tt[0];
        } else {                // last matching (forward t_ref)
            bool found = false;
            for (int base = NEV - 1; base >= 0 && !found; base -= 32) {
                int idx = base - lane;
                bool hit = (idx >= 0) && (pp[idx] == want);
                unsigned bal = __ballot_sync(0xffffffffu, hit);
                if (bal) {
                    if (lane == 0) g_tref[b][m][1] = tt[base - (__ffs(bal) - 1)];
                    found = true;
                }
            }
            if (!found && lane == 0) g_tref[b][m][1] = tt[NEV - 1];
        }
    }
}

// ---------------------------------------------------------------------------
// Bilinear scatter: even x0 -> one v4 per row; odd x0 -> two v2 per row.
// ---------------------------------------------------------------------------
__device__ __forceinline__ void scatter(float2* __restrict__ img, int W,
                                        float xl, float yl, float t_,
                                        float fx, float fy, float t) {
    float xf = fminf(fmaxf(fmaf(t_, fx, xl), 0.f), (float)(W - 1));
    float yf = fminf(fmaxf(fmaf(t_, fy, yl), 0.f), (float)(W - 1));
    float x0 = floorf(xf), y0 = floorf(yf);
    float x0w = xf - x0, y0w = yf - y0;
    float x1w = 1.f - x0w, y1w = 1.f - y0w;
    int x0i = (int)x0, y0i = (int)y0;
    int y1i = min(y0i + 1, W - 1);
    float nA = x1w * t;
    float nB = x0w * t;
    if (!(x0i & 1)) {
        red4(img + (y0i * W + x0i), nA * y1w, 1.f, nB * y1w, 1.f);
        red4(img + (y1i * W + x0i), nA * y0w, 1.f, nB * y0w, 1.f);
    } else {
        int x1i = min(x0i + 1, W - 1);
        red2(img + (y0i * W + x0i), nA * y1w, 1.f);
        red2(img + (y0i * W + x1i), nB * y1w, 1.f);
        red2(img + (y1i * W + x0i), nA * y0w, 1.f);
        red2(img + (y1i * W + x1i), nB * y0w, 1.f);
    }
}

// ---------------------------------------------------------------------------
// k_main roles: [0,NB_SM) smoothness | rest events   (unchanged control)
// ---------------------------------------------------------------------------
#define NB_EV 3125
__device__ __constant__ int c_smb[5] = {0, 384, 480, 504, 512};

__global__ void __launch_bounds__(256)
k_main(const float* __restrict__ f0, const float* __restrict__ f1,
       const float* __restrict__ f2, const float* __restrict__ f3,
       const int* __restrict__ xs, const int* __restrict__ ys,
       const float* __restrict__ ts, const int* __restrict__ ps) {
    int tid = threadIdx.x;
    if (blockIdx.x < NB_SM) {
        int l, b0, b1;
        if (blockIdx.x < c_smb[1])      { l = 3; b0 = c_smb[0]; b1 = c_smb[1]; }
        else if (blockIdx.x < c_smb[2]) { l = 2; b0 = c_smb[1]; b1 = c_smb[2]; }
        else if (blockIdx.x < c_smb[3]) { l = 1; b0 = c_smb[2]; b1 = c_smb[3]; }
        else                            { l = 0; b0 = c_smb[3]; b1 = c_smb[4]; }
        const float* f = (l == 3) ? f3 : (l == 2) ? f2 : (l == 1) ? f1 : f0;
        const int W = 32 << l;
        const int HW = W * W;
        const int n = 16 * HW;
        float inv_lr = 1.f / (16.f * W * (W - 1));
        float inv_d  = 1.f / (16.f * (W - 1) * (W - 1));
        int stride = (b1 - b0) * 256;
        float acc = 0.f;
        for (int i = (blockIdx.x - b0) * 256 + tid; i < n; i += stride) {
            int pix = i & (HW - 1);
            int col = pix & (W - 1);
            int row = pix >> (5 + l);
            float v = f[i];
            bool hr = (col < W - 1), hd = (row < W - 1);
            if (hr) {
                float r = f[i + 1];
                float d1 = r - v;
                acc += __powf(d1 * d1 + 1e-6f, 0.45f) * inv_lr;
                if (hd) {
                    float dn = f[i + W];
                    float dr = f[i + W + 1];
                    float t1 = dr - v;
                    float t2 = r - dn;
                    acc += (__powf(t1 * t1 + 1e-6f, 0.45f) +
                            __powf(t2 * t2 + 1e-6f, 0.45f)) * inv_d;
                }
            }
            if (hd) {
                float dn = f[i + W];
                float d2 = dn - v;
                acc += __powf(d2 * d2 + 1e-6f, 0.45f) * inv_lr;
            }
        }
        double s = block_reduce(acc);
        if (tid == 0) g_part_sm[blockIdx.x] = s;
    } else {
        int idx = (blockIdx.x - NB_SM) * 256 + tid;
        if (idx >= B * NEV) return;
        int b = idx / NEV;
        int x = xs[idx], y = ys[idx];
        float t = ts[idx];
        int m = (ps[idx] == 1) ? 0 : 1;
        float tfw = g_tref[b][m][1] - t + EPSF;
        float tbw = g_tref[b][m][0] - t - EPSF;
        const float* fl[4] = {f0, f1, f2, f3};
#pragma unroll
        for (int l = 0; l < 4; l++) {
            const int W = 32 << l;
            const int HW = W * W;
            int xl = x >> (3 - l), yl = y >> (3 - l);
            const float* fp = fl[l] + (size_t)b * 2 * HW + yl * W + xl;
            float fx = __ldg(fp);
            float fy = __ldg(fp + HW);
            float2* base = g_accum + c_loff[l];
            scatter(base + (size_t)((b * 2 + 1) * 2 + m) * HW, W,
                    (float)xl, (float)yl, tfw, fx, fy, t);
            scatter(base + (size_t)((b * 2 + 0) * 2 + m) * HW, W,
                    (float)xl, (float)yl, tbw, fx, fy, t);
        }
    }
}

// ---------------------------------------------------------------------------
// k_evreduce: MLP-4 batched loads; sqrt((n/d')^2+1e-6)=h*rsqrt(h*d'^2).
// Last block folds in smoothness/WD partials and writes the scalar result.
// ---------------------------------------------------------------------------
__device__ __forceinline__ float ev_term2(float4 v) {
    float d0 = v.y + EPSF, d1 = v.w + EPSF;
    float d0s = d0 * d0,   d1s = d1 * d1;
    float h0 = fmaf(v.x, v.x, 1e-6f * d0s);
    float h1 = fmaf(v.z, v.z, 1e-6f * d1s);
    return h0 * rsqrt_approx(h0 * d0s) + h1 * rsqrt_approx(h1 * d1s);
}

__global__ void __launch_bounds__(256) k_evreduce(float* __restrict__ out) {
    const float4* acc4 = (const float4*)g_accum;
    const int n4 = ACCUM_F2 / 2;    // 1,392,640
    float a0 = 0.f, a1 = 0.f, a2 = 0.f, a3 = 0.f;
    for (int base = blockIdx.x * 1024 + threadIdx.x; base < n4; base += NB_ER * 1024) {
        int i1 = base + 256, i2 = base + 512, i3 = base + 768;
        float4 v0 = acc4[base];
        bool g1 = i1 < n4, g2 = i2 < n4, g3 = i3 < n4;
        float4 v1 = g1 ? acc4[i1] : make_float4(0.f, 1.f, 0.f, 1.f);
        float4 v2 = g2 ? acc4[i2] : make_float4(0.f, 1.f, 0.f, 1.f);
        float4 v3 = g3 ? acc4[i3] : make_float4(0.f, 1.f, 0.f, 1.f);
        a0 += ev_term2(v0);
        if (g1) a1 += ev_term2(v1);
        if (g2) a2 += ev_term2(v2);
        if (g3) a3 += ev_term2(v3);
    }
    double s = block_reduce((a0 + a1) + (a2 + a3));
    __shared__ bool is_last;
    if (threadIdx.x == 0) {
        g_part_er[blockIdx.x] = s;
        __threadfence();
        unsigned r = atomicAdd(&g_done, 1u);
        is_last = (r == NB_ER - 1);
    }
    __syncthreads();
    if (is_last) {
        __shared__ double swarp[8];
        double tot = 0.0;
        for (int i = threadIdx.x; i < NB_ER; i += 256) tot += g_part_er[i];
        for (int i = threadIdx.x; i < NB_SM; i += 256) tot += 6.25 * g_part_sm[i];
        for (int i = threadIdx.x; i < NB_WD; i += 256) tot += 5.0e-5 * g_part_wd[i];
        for (int o = 16; o > 0; o >>= 1) tot += __shfl_down_sync(0xffffffffu, tot, o);
        if ((threadIdx.x & 31) == 0) swarp[threadIdx.x >> 5] = tot;
        __syncthreads();
        if (threadIdx.x == 0) {
            double r = 0.0;
            for (int w = 0; w < 8; w++) r += swarp[w];
            out[0] = (float)r;
        }
    }
}

// ---------------------------------------------------------------------------
extern "C" void kernel_launch(void* const* d_in, const int* in_sizes, int n_in,
                              void* d_out, int out_size) {
    const float* f0 = (const float*)d_in[0];
    const float* f1 = (const float*)d_in[1];
    const float* f2 = (const float*)d_in[2];
    const float* f3 = (const float*)d_in[3];
    const int*   xs = (const int*)d_in[4];
    const int*   ys = (const int*)d_in[5];
    const float* ts = (const float*)d_in[6];
    const int*   ps = (const int*)d_in[7];
    const float* params = (const float*)d_in[10];
    float* out = (float*)d_out;

    k_pre<<<PRE_ZERO + PRE_WD + PRE_TREF, 256>>>(ts, ps, params);
    k_main<<<NB_SM + NB_EV, 256>>>(f0, f1, f2, f3, xs, ys, ts, ps);
    k_evreduce<<<NB_ER, 256>>>(out);
}